// round 1
// baseline (speedup 1.0000x reference)
#include <cuda_runtime.h>
#include <cuda_fp16.h>
#include <cstdint>

// Problem constants
#define M_DIM 4096
#define N_DIM 11008
#define K_DIM 4096
#define GROUP 128
#define N_GROUPS 32   // K_DIM / GROUP

// Scratch (device globals; no allocation allowed)
__device__ __half g_xT[(size_t)M_DIM * K_DIM];   // transformed x, fp16, row-major [M][K]
__device__ __half g_W[(size_t)N_DIM * K_DIM];    // dequantized W, fp16, row-major [N][K]

// ---------------------------------------------------------------------------
// Kernel 1: x' = H (s2 * H (s1 * x)), per group of 128, scaled 1/128, -> fp16
// grid: (32 groups, 4096 rows), block: 128 threads
// ---------------------------------------------------------------------------
__global__ void transform_x_kernel(const float* __restrict__ x,
                                   const float* __restrict__ s1,
                                   const float* __restrict__ s2,
                                   __half* __restrict__ xt) {
    __shared__ float buf[GROUP];
    const int t = threadIdx.x;
    const int grp = blockIdx.x;
    const int row = blockIdx.y;
    const size_t base = (size_t)row * K_DIM + grp * GROUP;

    float v = x[base + t] * __ldg(&s1[t]);
    buf[t] = v;
    __syncthreads();

    // FWHT #1
#pragma unroll
    for (int h = 1; h < GROUP; h <<= 1) {
        float a = buf[t];
        float b = buf[t ^ h];
        __syncthreads();
        buf[t] = (t & h) ? (b - a) : (a + b);
        __syncthreads();
    }

    float u = buf[t] * __ldg(&s2[t]);
    __syncthreads();
    buf[t] = u;
    __syncthreads();

    // FWHT #2
#pragma unroll
    for (int h = 1; h < GROUP; h <<= 1) {
        float a = buf[t];
        float b = buf[t ^ h];
        __syncthreads();
        buf[t] = (t & h) ? (b - a) : (a + b);
        __syncthreads();
    }

    xt[base + t] = __float2half(buf[t] * (1.0f / 128.0f));
}

// ---------------------------------------------------------------------------
// Kernel 2: dequant W[o][k] = norms[o][k/128] * centroids[nibble(packed)]
// One thread per packed byte (two output halves, written as __half2).
// ---------------------------------------------------------------------------
__global__ void dequant_kernel(const int* __restrict__ pw,
                               const float* __restrict__ norms,
                               const float* __restrict__ cent,
                               __half* __restrict__ W) {
    __shared__ float c[16];
    if (threadIdx.x < 16) c[threadIdx.x] = cent[threadIdx.x];
    __syncthreads();

    const int idx = blockIdx.x * blockDim.x + threadIdx.x;  // 0 .. 11008*2048-1
    const int o = idx >> 11;         // / 2048
    const int p = idx & 2047;        // byte within row
    const unsigned b = ((unsigned)pw[idx]) & 0xFFu;
    const float norm = __ldg(&norms[o * N_GROUPS + (p >> 6)]);  // group = p/64
    __half2 h2 = __floats2half2_rn(c[b & 15u] * norm, c[b >> 4] * norm);
    reinterpret_cast<__half2*>(W)[idx] = h2;
}

// ---------------------------------------------------------------------------
// Kernel 3: GEMM  C[M][N] = A[M][K] * B[N][K]^T + bias[N]
// fp16 inputs, fp32 accumulate. mma.sync m16n8k16, cp.async double buffer.
// Block tile 128x128x32, 8 warps (2x4), warp tile 64x32.
// ---------------------------------------------------------------------------
#define BM 128
#define BN 128
#define BK 32
#define KS 40           // BK + 8 halves pad (keeps 16B alignment, kills conflicts)

__device__ __forceinline__ void cp16(void* smem, const void* gmem) {
    uint32_t s = (uint32_t)__cvta_generic_to_shared(smem);
    asm volatile("cp.async.cg.shared.global [%0], [%1], 16;\n" :: "r"(s), "l"(gmem));
}
__device__ __forceinline__ void cp_commit() {
    asm volatile("cp.async.commit_group;\n");
}
__device__ __forceinline__ void ldsm4(uint32_t* r, const void* p) {
    uint32_t addr = (uint32_t)__cvta_generic_to_shared(p);
    asm volatile("ldmatrix.sync.aligned.m8n8.x4.shared.b16 {%0,%1,%2,%3}, [%4];\n"
                 : "=r"(r[0]), "=r"(r[1]), "=r"(r[2]), "=r"(r[3]) : "r"(addr));
}
__device__ __forceinline__ void mma16816(float* c, const uint32_t* a, uint32_t b0, uint32_t b1) {
    asm volatile(
        "mma.sync.aligned.m16n8k16.row.col.f32.f16.f16.f32 "
        "{%0,%1,%2,%3}, {%4,%5,%6,%7}, {%8,%9}, {%0,%1,%2,%3};\n"
        : "+f"(c[0]), "+f"(c[1]), "+f"(c[2]), "+f"(c[3])
        : "r"(a[0]), "r"(a[1]), "r"(a[2]), "r"(a[3]), "r"(b0), "r"(b1));
}

__global__ __launch_bounds__(256, 2) void gemm_kernel(
    const __half* __restrict__ A, const __half* __restrict__ B,
    const float* __restrict__ bias, float* __restrict__ C) {
    __shared__ __half As[2][BM * KS];
    __shared__ __half Bs[2][BN * KS];

    const int tid = threadIdx.x;
    const int wid = tid >> 5;
    const int lane = tid & 31;
    const int wm = (wid >> 2) * 64;   // warp row offset in block tile
    const int wn = (wid & 3) * 32;    // warp col offset in block tile
    const int bm = blockIdx.y * BM;
    const int bn = blockIdx.x * BN;

    const __half* Ag = A + (size_t)bm * K_DIM;
    const __half* Bg = B + (size_t)bn * K_DIM;

    float acc[4][4][4];
#pragma unroll
    for (int i = 0; i < 4; i++)
#pragma unroll
        for (int j = 0; j < 4; j++)
#pragma unroll
            for (int k = 0; k < 4; k++) acc[i][j][k] = 0.0f;

    // per-thread gmem->smem chunk mapping: 512 16B chunks each for A and B
    const int c0 = tid;               // chunk ids tid, tid+256
    // ldmatrix lane addressing
    const int a_row = lane & 15;
    const int a_col = (lane >> 4) * 8;
    const int b_row = (lane & 7) + (lane >> 4) * 8;
    const int b_col = ((lane >> 3) & 1) * 8;

    const int KT = K_DIM / BK;  // 128

    // prologue: load tile 0
    {
        const int k0 = 0;
#pragma unroll
        for (int i = 0; i < 2; i++) {
            int c = c0 + i * 256;
            int row = c >> 2, col = (c & 3) * 8;
            cp16(&As[0][row * KS + col], Ag + (size_t)row * K_DIM + k0 + col);
            cp16(&Bs[0][row * KS + col], Bg + (size_t)row * K_DIM + k0 + col);
        }
        cp_commit();
    }

    for (int kt = 0; kt < KT; ++kt) {
        const int cur = kt & 1;
        if (kt + 1 < KT) {
            const int nxt = cur ^ 1;
            const int k0 = (kt + 1) * BK;
#pragma unroll
            for (int i = 0; i < 2; i++) {
                int c = c0 + i * 256;
                int row = c >> 2, col = (c & 3) * 8;
                cp16(&As[nxt][row * KS + col], Ag + (size_t)row * K_DIM + k0 + col);
                cp16(&Bs[nxt][row * KS + col], Bg + (size_t)row * K_DIM + k0 + col);
            }
            cp_commit();
            asm volatile("cp.async.wait_group 1;\n");
        } else {
            asm volatile("cp.async.wait_group 0;\n");
        }
        __syncthreads();

        // compute on stage `cur`
#pragma unroll
        for (int ks = 0; ks < 2; ks++) {
            uint32_t afr[4][4];
#pragma unroll
            for (int mt = 0; mt < 4; mt++) {
                const __half* p = &As[cur][(wm + mt * 16 + a_row) * KS + ks * 16 + a_col];
                ldsm4(afr[mt], p);
            }
            uint32_t bfr[2][4];
#pragma unroll
            for (int nb = 0; nb < 2; nb++) {
                const __half* p = &Bs[cur][(wn + nb * 16 + b_row) * KS + ks * 16 + b_col];
                ldsm4(bfr[nb], p);
            }
#pragma unroll
            for (int mt = 0; mt < 4; mt++) {
#pragma unroll
                for (int nt = 0; nt < 4; nt++) {
                    uint32_t bb0 = bfr[nt >> 1][(nt & 1) * 2];
                    uint32_t bb1 = bfr[nt >> 1][(nt & 1) * 2 + 1];
                    mma16816(acc[mt][nt], afr[mt], bb0, bb1);
                }
            }
        }
        __syncthreads();
    }

    // epilogue
    const int groupID = lane >> 2;
    const int tq = lane & 3;
#pragma unroll
    for (int mt = 0; mt < 4; mt++) {
#pragma unroll
        for (int nt = 0; nt < 4; nt++) {
            int row0 = bm + wm + mt * 16 + groupID;
            int col0 = bn + wn + nt * 8 + tq * 2;
            float bz0 = __ldg(&bias[col0]);
            float bz1 = __ldg(&bias[col0 + 1]);
            size_t o0 = (size_t)row0 * N_DIM + col0;
            size_t o1 = (size_t)(row0 + 8) * N_DIM + col0;
            C[o0]     = acc[mt][nt][0] + bz0;
            C[o0 + 1] = acc[mt][nt][1] + bz1;
            C[o1]     = acc[mt][nt][2] + bz0;
            C[o1 + 1] = acc[mt][nt][3] + bz1;
        }
    }
}

// ---------------------------------------------------------------------------
// Launch
// inputs: 0=x f32[4096,4096], 1=packed_weight i32[11008,2048], 2=norms f32[11008,32],
//         3=centroids f32[16], 4=signs1 f32[128], 5=signs2 f32[128], 6=bias f32[11008]
// output: f32 [4096, 11008]
// ---------------------------------------------------------------------------
extern "C" void kernel_launch(void* const* d_in, const int* in_sizes, int n_in,
                              void* d_out, int out_size) {
    const float* x      = (const float*)d_in[0];
    const int*   pw     = (const int*)d_in[1];
    const float* norms  = (const float*)d_in[2];
    const float* cent   = (const float*)d_in[3];
    const float* s1     = (const float*)d_in[4];
    const float* s2     = (const float*)d_in[5];
    const float* bias   = (const float*)d_in[6];
    float* out = (float*)d_out;

    __half* xt;
    __half* W;
    cudaGetSymbolAddress((void**)&xt, g_xT);
    cudaGetSymbolAddress((void**)&W, g_W);

    // 1) transform x
    {
        dim3 grid(N_GROUPS, M_DIM);
        transform_x_kernel<<<grid, GROUP>>>(x, s1, s2, xt);
    }
    // 2) dequantize W
    {
        int total = N_DIM * (K_DIM / 2);   // packed bytes = 11008*2048
        dequant_kernel<<<total / 256, 256>>>(pw, norms, cent, W);
    }
    // 3) GEMM
    {
        dim3 grid(N_DIM / BN, M_DIM / BM);  // 86 x 32
        gemm_kernel<<<grid, 256>>>(xt, W, bias, out);
    }
}

// round 3
// speedup vs baseline: 1.4951x; 1.4951x over previous
#include <cuda_runtime.h>
#include <cuda_fp16.h>
#include <cstdint>

// ---------------------------------------------------------------------------
// Problem constants
// ---------------------------------------------------------------------------
#define M_DIM 4096
#define N_DIM 11008
#define K_DIM 4096
#define GROUP 128

#define BM 128            // CTA M tile
#define BN 256            // CTA N tile
#define KC 64             // K halves per pipeline chunk (= 128 bytes per row)
#define NKC (K_DIM / KC)  // 64 chunks
#define NMT (M_DIM / BM)  // 32
#define NNT (N_DIM / BN)  // 43

#define A_BLK_BYTES (BM * 128)       // 16384
#define B_BLK_BYTES (BN * 128)       // 32768
#define STAGE_BYTES (A_BLK_BYTES + B_BLK_BYTES)  // 49152
#define NSTAGES 4
#define SM_TOTAL (2048 + NSTAGES * STAGE_BYTES)  // 198656

// Tiled+swizzled scratch in GMEM (device globals; 16B aligned via uint4)
__device__ uint4 g_A[(size_t)NMT * NKC * A_BLK_BYTES / 16];   // 33.5 MB
__device__ uint4 g_B[(size_t)NNT * NKC * B_BLK_BYTES / 16];   // 90.2 MB

// SW128 swizzle (relative to 1KB-aligned tile start)
__host__ __device__ __forceinline__ uint32_t swz128(uint32_t off) {
    return off ^ ((off >> 3) & 0x70u);
}

// ---------------------------------------------------------------------------
// PTX helpers (sm_90-level only; tcgen05 is NOT available in this build)
// ---------------------------------------------------------------------------
__device__ __forceinline__ uint32_t smem_u32(const void* p) {
    uint32_t a;
    asm("{ .reg .u64 t; cvta.to.shared.u64 t, %1; cvt.u32.u64 %0, t; }" : "=r"(a) : "l"(p));
    return a;
}

#define MBAR_INIT(addr, cnt) \
    asm volatile("mbarrier.init.shared.b64 [%0], %1;" :: "r"(addr), "r"(cnt) : "memory")

#define MBAR_EXPECT_TX(addr, bytes) \
    asm volatile("mbarrier.arrive.expect_tx.shared.b64 _, [%0], %1;" :: "r"(addr), "r"(bytes) : "memory")

#define MBAR_ARRIVE(addr) \
    asm volatile("mbarrier.arrive.shared.b64 _, [%0];" :: "r"(addr) : "memory")

#define MBAR_WAIT(addr, parity) do {                                        \
    uint32_t _m = (addr); uint32_t _p = (parity); uint32_t _d;              \
    asm volatile("{\n\t.reg .pred p;\n\t"                                   \
        "mbarrier.try_wait.parity.acquire.cta.shared::cta.b64 p, [%1], %2;\n\t" \
        "selp.b32 %0, 1, 0, p;\n\t}"                                        \
        : "=r"(_d) : "r"(_m), "r"(_p) : "memory");                          \
    if (!_d) {                                                              \
        asm volatile("{\n\t.reg .pred P1;\n\t"                              \
            "W0_%=:\n\t"                                                    \
            "mbarrier.try_wait.parity.acquire.cta.shared::cta.b64 P1, [%0], %1, 0x989680;\n\t" \
            "@P1 bra.uni W1_%=;\n\t"                                        \
            "bra.uni W0_%=;\n\t"                                            \
            "W1_%=:\n\t}" :: "r"(_m), "r"(_p) : "memory");                  \
    }                                                                       \
} while (0)

__device__ __forceinline__ void bulk_ld(uint32_t dst, const void* src, uint32_t bytes,
                                        uint32_t mbar) {
    asm volatile(
        "cp.async.bulk.shared::cluster.global.mbarrier::complete_tx::bytes [%0], [%1], %2, [%3];"
        :: "r"(dst), "l"(src), "r"(bytes), "r"(mbar) : "memory");
}

__device__ __forceinline__ void ldsm4(uint32_t* r, uint32_t addr) {
    asm volatile("ldmatrix.sync.aligned.m8n8.x4.shared.b16 {%0,%1,%2,%3}, [%4];\n"
                 : "=r"(r[0]), "=r"(r[1]), "=r"(r[2]), "=r"(r[3]) : "r"(addr));
}
__device__ __forceinline__ void mma16816(float* c, const uint32_t* a, uint32_t b0, uint32_t b1) {
    asm volatile(
        "mma.sync.aligned.m16n8k16.row.col.f32.f16.f16.f32 "
        "{%0,%1,%2,%3}, {%4,%5,%6,%7}, {%8,%9}, {%0,%1,%2,%3};\n"
        : "+f"(c[0]), "+f"(c[1]), "+f"(c[2]), "+f"(c[3])
        : "r"(a[0]), "r"(a[1]), "r"(a[2]), "r"(a[3]), "r"(b0), "r"(b1));
}

// ---------------------------------------------------------------------------
// Kernel 1: x' = H (s2 * H (s1 * x)) / 128, warp-shuffle FWHT, tiled swizzled out
// ---------------------------------------------------------------------------
__global__ __launch_bounds__(256) void transform_x_kernel(
    const float* __restrict__ x, const float* __restrict__ s1,
    const float* __restrict__ s2, unsigned char* __restrict__ At) {
    const int lane = threadIdx.x & 31;
    const int wrp = threadIdx.x >> 5;
    const int pair = blockIdx.x * 8 + wrp;  // 0 .. 131071
    const int row = pair >> 5;
    const int grp = pair & 31;

    const float4 xv = *(const float4*)(x + (size_t)row * K_DIM + grp * GROUP + lane * 4);
    const float4 s1v = *(const float4*)(s1 + lane * 4);
    const float4 s2v = *(const float4*)(s2 + lane * 4);

    float v[4] = { xv.x * s1v.x, xv.y * s1v.y, xv.z * s1v.z, xv.w * s1v.w };

#pragma unroll
    for (int pass = 0; pass < 2; pass++) {
        float t0 = v[0] + v[1], t1 = v[0] - v[1];
        float t2 = v[2] + v[3], t3 = v[2] - v[3];
        v[0] = t0 + t2; v[2] = t0 - t2;
        v[1] = t1 + t3; v[3] = t1 - t3;
#pragma unroll
        for (int xm = 1; xm <= 16; xm <<= 1) {
            bool hi = (lane & xm) != 0;
#pragma unroll
            for (int j = 0; j < 4; j++) {
                float o = __shfl_xor_sync(0xFFFFFFFFu, v[j], xm);
                v[j] = hi ? (o - v[j]) : (v[j] + o);
            }
        }
        if (pass == 0) {
            v[0] *= s2v.x; v[1] *= s2v.y; v[2] *= s2v.z; v[3] *= s2v.w;
        }
    }

    const float sc = 1.0f / 128.0f;
    __half2 h01 = __floats2half2_rn(v[0] * sc, v[1] * sc);
    __half2 h23 = __floats2half2_rn(v[2] * sc, v[3] * sc);

    const int mt = row >> 7, r = row & 127;
    const int e = 4 * lane;
    const int kc = grp * 2 + (e >> 6);
    const int c = e & 63;
    const size_t base = ((size_t)mt * NKC + kc) * A_BLK_BYTES;
    const uint32_t off = swz128((uint32_t)(r * 128 + c * 2));
    uint2 val = { *(uint32_t*)&h01, *(uint32_t*)&h23 };
    *(uint2*)(At + base + off) = val;
}

// ---------------------------------------------------------------------------
// Kernel 2: dequant W -> tiled swizzled layout. 1 thread per packed byte.
// ---------------------------------------------------------------------------
__global__ __launch_bounds__(256) void dequant_kernel(
    const int* __restrict__ pw, const float* __restrict__ norms,
    const float* __restrict__ cent, unsigned char* __restrict__ Bt) {
    __shared__ float c[16];
    if (threadIdx.x < 16) c[threadIdx.x] = cent[threadIdx.x];
    __syncthreads();

    const int idx = blockIdx.x * 256 + threadIdx.x;
    const int o = idx >> 11;
    const int p = idx & 2047;
    const unsigned b = ((unsigned)pw[idx]) & 0xFFu;
    const float norm = __ldg(&norms[o * 32 + (p >> 6)]);
    __half2 h2 = __floats2half2_rn(c[b & 15u] * norm, c[b >> 4] * norm);

    const int nt = o >> 8, r = o & 255;
    const int kc = p >> 5;
    const uint32_t off = swz128((uint32_t)(r * 128 + (p & 31) * 4));
    const size_t base = ((size_t)nt * NKC + kc) * B_BLK_BYTES;
    *(uint32_t*)(Bt + base + off) = *(uint32_t*)&h2;
}

// ---------------------------------------------------------------------------
// Kernel 3: mma.sync GEMM, 128x256 CTA tile, 8 compute warps (64x64 each)
// + 1 producer warp; 4-stage cp.async.bulk pipeline, no __syncthreads in loop.
// ---------------------------------------------------------------------------
extern __shared__ unsigned char dsm[];

__global__ __launch_bounds__(288, 1) void gemm_kernel(
    const unsigned char* __restrict__ At, const unsigned char* __restrict__ Bt,
    const float* __restrict__ bias, float* __restrict__ C) {
    const int tid = threadIdx.x;
    const int wid = tid >> 5;
    const int lane = tid & 31;
    const uint32_t sb = (smem_u32(dsm) + 1023) & ~1023u;  // 1KB-align for swizzle

    const int mt = blockIdx.y;
    const int nt = blockIdx.x;
    const unsigned char* Ag = At + (size_t)mt * NKC * A_BLK_BYTES;
    const unsigned char* Bg = Bt + (size_t)nt * NKC * B_BLK_BYTES;

    // mbarriers: full[s] at sb+8s (count 1, tx), empty[s] at sb+32+8s (count 8)
    if (tid == 0) {
#pragma unroll
        for (int s = 0; s < NSTAGES; s++) {
            MBAR_INIT(sb + 8 * s, 1);
            MBAR_INIT(sb + 32 + 8 * s, 8);
        }
        asm volatile("fence.proxy.async.shared::cta;" ::: "memory");
    }
    __syncthreads();

    if (wid == 8) {
        // ---------------- producer warp (lane 0 only) ----------------
        if (lane == 0) {
            for (int j = 0; j < NKC; j++) {
                const int s = j & 3;
                if (j >= NSTAGES) {
                    MBAR_WAIT(sb + 32 + 8 * s, ((j >> 2) - 1) & 1);
                }
                const uint32_t full = sb + 8 * s;
                MBAR_EXPECT_TX(full, STAGE_BYTES);
                const uint32_t st = sb + 1024 + s * STAGE_BYTES;
                bulk_ld(st, Ag + (size_t)j * A_BLK_BYTES, A_BLK_BYTES, full);
                bulk_ld(st + A_BLK_BYTES, Bg + (size_t)j * B_BLK_BYTES, B_BLK_BYTES, full);
            }
        }
        return;
    }

    // ---------------- compute warps 0..7: warp tile 64x64 ----------------
    const int wm = (wid >> 2) * 64;   // 0 or 64
    const int wn = (wid & 3) * 64;    // 0,64,128,192

    float acc[4][8][4];
#pragma unroll
    for (int i = 0; i < 4; i++)
#pragma unroll
        for (int j = 0; j < 8; j++)
#pragma unroll
            for (int k = 0; k < 4; k++) acc[i][j][k] = 0.0f;

    // ldmatrix lane addressing (precomputed row*128 part, swizzle applied per use)
    const int a_row = lane & 15;
    const int a_colh = (lane >> 4) * 8;          // half-index within k16
    const int b_row = (lane & 7) + (lane >> 4) * 8;
    const int b_colh = ((lane >> 3) & 1) * 8;

    for (int j = 0; j < NKC; j++) {
        const int s = j & 3;
        MBAR_WAIT(sb + 8 * s, (j >> 2) & 1);
        const uint32_t as = sb + 1024 + s * STAGE_BYTES;
        const uint32_t bs = as + A_BLK_BYTES;

#pragma unroll
        for (int ks = 0; ks < 4; ks++) {
            uint32_t afr[4][4];
#pragma unroll
            for (int m = 0; m < 4; m++) {
                uint32_t off = swz128((uint32_t)((wm + m * 16 + a_row) * 128 +
                                                 (ks * 16 + a_colh) * 2));
                ldsm4(afr[m], as + off);
            }
            uint32_t bfr[4][4];
#pragma unroll
            for (int nb = 0; nb < 4; nb++) {
                uint32_t off = swz128((uint32_t)((wn + nb * 16 + b_row) * 128 +
                                                 (ks * 16 + b_colh) * 2));
                ldsm4(bfr[nb], bs + off);
            }
#pragma unroll
            for (int m = 0; m < 4; m++) {
#pragma unroll
                for (int n = 0; n < 8; n++) {
                    mma16816(acc[m][n], afr[m], bfr[n >> 1][(n & 1) * 2],
                             bfr[n >> 1][(n & 1) * 2 + 1]);
                }
            }
        }
        if (lane == 0) MBAR_ARRIVE(sb + 32 + 8 * s);
    }

    // ---------------- epilogue ----------------
    const int gid = lane >> 2;
    const int tq = lane & 3;
    const int bm = mt * BM, bn = nt * BN;
#pragma unroll
    for (int m = 0; m < 4; m++) {
        const int row0 = bm + wm + m * 16 + gid;
#pragma unroll
        for (int n = 0; n < 8; n++) {
            const int col0 = bn + wn + n * 8 + tq * 2;
            const float bz0 = __ldg(&bias[col0]);
            const float bz1 = __ldg(&bias[col0 + 1]);
            float2 v0 = { acc[m][n][0] + bz0, acc[m][n][1] + bz1 };
            float2 v1 = { acc[m][n][2] + bz0, acc[m][n][3] + bz1 };
            *(float2*)(C + (size_t)row0 * N_DIM + col0) = v0;
            *(float2*)(C + (size_t)(row0 + 8) * N_DIM + col0) = v1;
        }
    }
}

// ---------------------------------------------------------------------------
// Launch
// ---------------------------------------------------------------------------
extern "C" void kernel_launch(void* const* d_in, const int* in_sizes, int n_in,
                              void* d_out, int out_size) {
    const float* x     = (const float*)d_in[0];
    const int*   pw    = (const int*)d_in[1];
    const float* norms = (const float*)d_in[2];
    const float* cent  = (const float*)d_in[3];
    const float* s1    = (const float*)d_in[4];
    const float* s2    = (const float*)d_in[5];
    const float* bias  = (const float*)d_in[6];
    float* out = (float*)d_out;

    unsigned char *At, *Bt;
    cudaGetSymbolAddress((void**)&At, g_A);
    cudaGetSymbolAddress((void**)&Bt, g_B);

    transform_x_kernel<<<(M_DIM * 32) / 8, 256>>>(x, s1, s2, At);
    dequant_kernel<<<(N_DIM * (K_DIM / 2)) / 256, 256>>>(pw, norms, cent, Bt);

    static bool attr_set = false;
    if (!attr_set) {
        cudaFuncSetAttribute(gemm_kernel, cudaFuncAttributeMaxDynamicSharedMemorySize,
                             SM_TOTAL);
        attr_set = true;
    }
    dim3 grid(NNT, NMT);
    gemm_kernel<<<grid, 288, SM_TOTAL>>>(At, Bt, bias, out);
}